// round 15
// baseline (speedup 1.0000x reference)
#include <cuda_runtime.h>

typedef unsigned long long u64;

#define N_TOT 2097152
#define TPB 128
#define PPB 512
#define K2_BLOCKS (N_TOT / PPB)          // 4096
#define K1_BLOCKS 2048

static __device__ float g_part[20 * K2_BLOCKS];
static __device__ float g_lrpart[K1_BLOCKS];
static __device__ float g_scale;
static __device__ float g_fin[20];
static __device__ unsigned int g_doneA;   // kA last-block counter (self-resetting)
static __device__ unsigned int g_doneB;   // k34 reduce counter (self-resetting)
static __device__ unsigned int g_flag;    // scale-ready flag (reset by kA each replay)
// weight blob: [0,300) pkT | [300,600) prkT | [600,640) w2 | [640,670) xc2 |
//              [670,700) pb12 | [700,703) packed scalars | pad to 704
static __device__ __align__(16) u64 g_wblob[704];

// ---------- packed f32x2 helpers ----------
__device__ __forceinline__ u64 pack2(float lo, float hi) {
    u64 r; asm("mov.b64 %0,{%1,%2};" : "=l"(r) : "f"(lo), "f"(hi)); return r;
}
__device__ __forceinline__ void unpack2(u64 v, float& lo, float& hi) {
    asm("mov.b64 {%0,%1},%2;" : "=f"(lo), "=f"(hi) : "l"(v));
}
__device__ __forceinline__ u64 fma2_(u64 a, u64 b, u64 c) {
    u64 d; asm("fma.rn.f32x2 %0,%1,%2,%3;" : "=l"(d) : "l"(a), "l"(b), "l"(c)); return d;
}
__device__ __forceinline__ u64 add2_(u64 a, u64 b) {
    u64 d; asm("add.rn.f32x2 %0,%1,%2;" : "=l"(d) : "l"(a), "l"(b)); return d;
}
__device__ __forceinline__ u64 mul2_(u64 a, u64 b) {
    u64 d; asm("mul.rn.f32x2 %0,%1,%2;" : "=l"(d) : "l"(a), "l"(b)); return d;
}
__device__ __forceinline__ u64 neg2_(u64 a) { return a ^ 0x8000000080000000ULL; }
__device__ __forceinline__ u64 sub2_(u64 a, u64 b) { return add2_(a, neg2_(b)); }

__device__ __forceinline__ float tanhap(float x) {
    float y; asm("tanh.approx.f32 %0,%1;" : "=f"(y) : "f"(x)); return y;
}
__device__ __forceinline__ float sig1(float x) {
    return fmaf(tanhap(0.5f * x), 0.5f, 0.5f);
}
__device__ __forceinline__ u64 sig2(u64 v) {
    float a, b; unpack2(v, a, b);
    return pack2(sig1(a), sig1(b));
}
__device__ __forceinline__ u64 tanh2(u64 v) {
    float a, b; unpack2(v, a, b);
    return pack2(tanhap(a), tanhap(b));
}
__device__ __forceinline__ u64 sqrt2_(u64 v) {
    float a, b; unpack2(v, a, b);
    float ra, rb;
    asm("sqrt.approx.f32 %0,%1;" : "=f"(ra) : "f"(a));
    asm("sqrt.approx.f32 %0,%1;" : "=f"(rb) : "f"(b));
    return pack2(ra, rb);
}
__device__ __forceinline__ u64 rsqrt2_(u64 v) {
    float a, b; unpack2(v, a, b);
    return pack2(rsqrtf(a), rsqrtf(b));
}
__device__ __forceinline__ u64 log2f2_(u64 v) {
    float a, b; unpack2(v, a, b);
    return pack2(__logf(a), __logf(b));
}

// ---------------- kA: fused lr-mean + xs_const + weight blob (last-block pattern) ----------------
__global__ void kA_setup(const float* __restrict__ lr,
                         const float* __restrict__ ht, const float* __restrict__ hg,
                         const float* __restrict__ pk, const float* __restrict__ prk,
                         const float* __restrict__ pb,
                         const float* __restrict__ w_dt, const float* __restrict__ b_dt,
                         const float* __restrict__ w_dn, const float* __restrict__ b_dn,
                         const float* __restrict__ w_bg, const float* __restrict__ b_bg,
                         const float* __restrict__ w_bl, const float* __restrict__ b_bl,
                         const float* __restrict__ gamma_p) {
    __shared__ float sh[256];
    __shared__ float s_xc[30];
    __shared__ float s_mean;
    __shared__ bool last;
    int t = threadIdx.x;
    float4 v = ((const float4*)lr)[blockIdx.x * 256 + t];
    sh[t] = (v.x + v.y) + (v.z + v.w);
    __syncthreads();
    for (int st = 128; st > 0; st >>= 1) { if (t < st) sh[t] += sh[t + st]; __syncthreads(); }
    if (t == 0) {
        g_lrpart[blockIdx.x] = sh[0];
        __threadfence();
        last = (atomicAdd(&g_doneA, 1u) == (unsigned)(K1_BLOCKS - 1));
    }
    __syncthreads();
    if (!last) return;

    // ----- sole surviving block: finalize everything -----
    float s2 = 0.f;
    #pragma unroll
    for (int k = 0; k < K1_BLOCKS / 256; k++) s2 += g_lrpart[t + k * 256];
    __syncthreads();
    sh[t] = s2; __syncthreads();
    for (int st = 128; st > 0; st >>= 1) { if (t < st) sh[t] += sh[t + st]; __syncthreads(); }
    if (t == 0) {
        s_mean = sh[0] * (1.f / (float)N_TOT);
        g_doneA = 0u;
        g_flag  = 0u;              // reset scale-ready flag for this replay
    }
    if (t < 30) {
        float a = pb[t];
        #pragma unroll
        for (int j = 0; j < 5; j++) a += ht[j] * pk[(9 + j) * 30 + t];
        #pragma unroll
        for (int j = 0; j < 5; j++) a += hg[j] * pk[(14 + j) * 30 + t];
        s_xc[t] = a;
    }
    __syncthreads();

    for (int k = t; k < 300; k += 256) {
        int j = k % 10, gu = k / 10;
        float wA = (j < 9) ? pk[j * 30 + gu] : 0.f;
        g_wblob[k] = pack2(wA, wA);
        float wB = prk[j * 30 + gu];
        g_wblob[300 + k] = pack2(wB, wB);
    }
    if (t < 10) {
        float a = w_dt[t]; g_wblob[600 + t] = pack2(a, a);
        float b = w_dn[t]; g_wblob[610 + t] = pack2(b, b);
        float c = w_bg[t]; g_wblob[620 + t] = pack2(c, c);
        float d = w_bl[t]; g_wblob[630 + t] = pack2(d, d);
    }
    if (t >= 32 && t < 62) {
        int u = t - 32;
        float a = s_xc[u];    g_wblob[640 + u] = pack2(a, a);
        float b = pb[30 + u]; g_wblob[670 + u] = pack2(b, b);
    }
    if (t == 0) {
        g_wblob[700] = pack2(s_mean, gamma_p[0]);
        g_wblob[701] = pack2(b_dt[0], b_dn[0]);
        g_wblob[702] = pack2(b_bg[0], b_bl[0]);
        g_wblob[703] = 0ULL;
    }
}

// ---------------- k2: main pass — byte-identical to R9 (best: 104.9us) ----------------
__global__ __launch_bounds__(TPB, 3)
void k2_main(const float* __restrict__ grads, const float* __restrict__ gbar,
             const float* __restrict__ lam, const float* __restrict__ hp_in,
             const float* __restrict__ nubar, const float* __restrict__ lr_in,
             float* __restrict__ out)
{
    __shared__ __align__(16) u64 s_w[704];
    __shared__ float s_red[20 * 4];
    __shared__ __align__(16) float s_hp[PPB * 11];   // row stride 11 -> conflict-free

    int t = threadIdx.x;
    int gp0 = blockIdx.x * PPB;
    int i = gp0 + t;          // params: i, i+128, i+256, i+384

    // ===== front-batched global loads (maximize MLP before any barrier) =====
    float4 hpv[10];
    {
        const float4* src = (const float4*)(hp_in + (size_t)gp0 * 10);
        #pragma unroll
        for (int q = 0; q < 10; q++) hpv[q] = src[t + q * TPB];
    }
    float grv[4], nbv[4], lrv[4];
    float gbv[16], lmv[16];
    #pragma unroll
    for (int q = 0; q < 4; q++) {
        grv[q] = grads[i + 128 * q];
        nbv[q] = nubar[i + 128 * q];
        lrv[q] = lr_in[i + 128 * q];
    }
    #pragma unroll
    for (int s = 0; s < 4; s++) {
        size_t off = (size_t)s * N_TOT + i;
        #pragma unroll
        for (int q = 0; q < 4; q++) {
            gbv[4 * s + q] = gbar[off + 128 * q];
            lmv[4 * s + q] = lam[off + 128 * q];
        }
    }

    // weight blob copy (gmem, L2-hot after wave 1): 352 float4
    {
        const float4* src = (const float4*)g_wblob;
        float4* dst = (float4*)s_w;
        #pragma unroll
        for (int q = 0; q < 3; q++) {
            int k = t + q * TPB;
            if (k < 352) dst[k] = src[k];
        }
    }

    // stage h_param into padded smem
    #pragma unroll
    for (int q = 0; q < 10; q++) {
        int k = t + q * TPB;
        float4 v = hpv[q];
        int i0 = 4 * k;
        s_hp[i0     + (i0    ) / 10] = v.x;
        s_hp[i0 + 1 + (i0 + 1) / 10] = v.y;
        s_hp[i0 + 2 + (i0 + 2) / 10] = v.z;
        s_hp[i0 + 3 + (i0 + 3) / 10] = v.w;
    }
    __syncthreads();

    const u64* s_pkT  = s_w;
    const u64* s_prkT = s_w + 300;
    const u64* s_w2   = s_w + 600;
    const u64* s_xc2  = s_w + 640;
    const u64* s_pb12 = s_w + 670;
    float ml, gmm, bdt, bdn, bbg, bbl;
    unpack2(s_w[700], ml, gmm);
    unpack2(s_w[701], bdt, bdn);
    unpack2(s_w[702], bbg, bbl);

    u64 hpA[10], hpB[10];
    {
        const float* h0 = s_hp + t * 11;
        #pragma unroll
        for (int u = 0; u < 10; u++) {
            hpA[u] = pack2(h0[u], h0[128 * 11 + u]);
            hpB[u] = pack2(h0[256 * 11 + u], h0[384 * 11 + u]);
        }
    }

    // four dots over h_param (packed, both pair-sets)
    u64 ddtA = pack2(bdt, bdt), ddtB = ddtA;
    u64 ddnA = pack2(bdn, bdn), ddnB = ddnA;
    u64 dbgA = pack2(bbg, bbg), dbgB = dbgA;
    u64 dblA = pack2(bbl, bbl), dblB = dblA;
    #pragma unroll
    for (int u = 0; u < 10; u++) {
        u64 w0 = s_w2[u], w1 = s_w2[10 + u], w2 = s_w2[20 + u], w3 = s_w2[30 + u];
        u64 hA = hpA[u], hB = hpB[u];
        ddtA = fma2_(hA, w0, ddtA); ddtB = fma2_(hB, w0, ddtB);
        ddnA = fma2_(hA, w1, ddnA); ddnB = fma2_(hB, w1, ddnB);
        dbgA = fma2_(hA, w2, dbgA); dbgB = fma2_(hB, w2, dbgB);
        dblA = fma2_(hA, w3, dblA); dblB = fma2_(hB, w3, dblB);
    }
    u64 b1A = sig2(dbgA), b1B = sig2(dbgB);
    u64 b2A = sig2(dblA), b2B = sig2(dblB);

    u64 gA = pack2(grv[0], grv[1]);
    u64 gB = pack2(grv[2], grv[3]);
    u64 g2A = mul2_(gA, gA), g2B = mul2_(gB, gB);

    float vals[20];
    u64 x2A[9], x2B[9];
    u64 llA[4], llB[4];
    #pragma unroll
    for (int s = 0; s < 4; s++) {
        size_t off = (size_t)s * N_TOT + i;
        u64 gbA = pack2(gbv[4 * s + 0], gbv[4 * s + 1]);
        u64 gbB = pack2(gbv[4 * s + 2], gbv[4 * s + 3]);
        u64 lmA = pack2(lmv[4 * s + 0], lmv[4 * s + 1]);
        u64 lmB = pack2(lmv[4 * s + 2], lmv[4 * s + 3]);
        u64 gbnA = fma2_(b1A, sub2_(gbA, gA), gA);
        u64 gbnB = fma2_(b1B, sub2_(gbB, gB), gB);
        u64 lmnA = fma2_(b2A, sub2_(lmA, g2A), g2A);
        u64 lmnB = fma2_(b2B, sub2_(lmB, g2B), g2B);
        float a, b;
        unpack2(gbnA, a, b); out[N_TOT + off] = a; out[N_TOT + off + 128] = b;
        unpack2(gbnB, a, b); out[N_TOT + off + 256] = a; out[N_TOT + off + 384] = b;
        unpack2(lmnA, a, b); out[5 * (size_t)N_TOT + off] = a; out[5 * (size_t)N_TOT + off + 128] = b;
        unpack2(lmnB, a, b); out[5 * (size_t)N_TOT + off + 256] = a; out[5 * (size_t)N_TOT + off + 384] = b;
        u64 mA = mul2_(gbnA, rsqrt2_(lmnA));
        u64 mB = mul2_(gbnB, rsqrt2_(lmnB));
        x2A[s] = mA; x2B[s] = mB;
        float m0, m1, m2, m3; unpack2(mA, m0, m1); unpack2(mB, m2, m3);
        vals[s] = (m0 + m1) + (m2 + m3);
        llA[s] = log2f2_(lmnA); llB[s] = log2f2_(lmnB);
        b1A = sqrt2_(b1A); b1B = sqrt2_(b1B);
        b2A = sqrt2_(b2A); b2B = sqrt2_(b2B);
    }
    {
        u64 q = pack2(0.25f, 0.25f);
        u64 lmAm = mul2_(q, add2_(add2_(llA[0], llA[1]), add2_(llA[2], llA[3])));
        u64 lmBm = mul2_(q, add2_(add2_(llB[0], llB[1]), add2_(llB[2], llB[3])));
        #pragma unroll
        for (int s = 0; s < 4; s++) {
            u64 aA = sub2_(llA[s], lmAm), aB = sub2_(llB[s], lmBm);
            x2A[4 + s] = aA; x2B[4 + s] = aB;
            float a0, a1, a2, a3; unpack2(aA, a0, a1); unpack2(aB, a2, a3);
            vals[4 + s] = (a0 + a1) + (a2 + a3);
        }
    }

    {
        float dt[4], dn[4];
        unpack2(ddtA, dt[0], dt[1]); unpack2(ddtB, dt[2], dt[3]);
        unpack2(ddnA, dn[0], dn[1]); unpack2(ddnB, dn[2], dn[3]);
        float nr[4];
        #pragma unroll
        for (int q = 0; q < 4; q++) {
            int p = i + 128 * q;
            float nu = dn[q] + nbv[q];
            out[(size_t)19 * N_TOT + 5 + p] = nu;
            out[(size_t)20 * N_TOT + 5 + p] = gmm * nbv[q] + (1.f - gmm) * nu;
            out[p] = __expf(lrv[q]) * dt[q];
            nr[q] = lrv[q] - ml;
        }
        vals[19] = dt[0] * dt[0] + dt[1] * dt[1] + dt[2] * dt[2] + dt[3] * dt[3];
        vals[8]  = (nr[0] + nr[1]) + (nr[2] + nr[3]);
        x2A[8] = pack2(nr[0], nr[1]);
        x2B[8] = pack2(nr[2], nr[3]);
    }

    // ---- per-param GRU: vectorized transposed weights (8 inputs vec + j=8 tail) ----
    #pragma unroll 1
    for (int u = 0; u < 10; u++) {
        u64 azA = s_xc2[u], arA = s_xc2[10 + u], ahA = s_xc2[20 + u];
        u64 azB = azA, arB = arA, ahB = ahA;
        u64 rzA = s_pb12[u], rrA = s_pb12[10 + u], rhA = s_pb12[20 + u];
        u64 rzB = rzA, rrB = rrA, rhB = rhA;

        const u64* bz = s_pkT + (size_t)u * 10;
        const u64* br = s_pkT + (size_t)(10 + u) * 10;
        const u64* bh = s_pkT + (size_t)(20 + u) * 10;
        #pragma unroll
        for (int jp = 0; jp < 4; jp++) {
            ulonglong2 wz = ((const ulonglong2*)bz)[jp];
            ulonglong2 wr = ((const ulonglong2*)br)[jp];
            ulonglong2 wh = ((const ulonglong2*)bh)[jp];
            u64 a0 = x2A[2 * jp], a1 = x2A[2 * jp + 1];
            u64 b0 = x2B[2 * jp], b1 = x2B[2 * jp + 1];
            azA = fma2_(a0, wz.x, azA); azA = fma2_(a1, wz.y, azA);
            azB = fma2_(b0, wz.x, azB); azB = fma2_(b1, wz.y, azB);
            arA = fma2_(a0, wr.x, arA); arA = fma2_(a1, wr.y, arA);
            arB = fma2_(b0, wr.x, arB); arB = fma2_(b1, wr.y, arB);
            ahA = fma2_(a0, wh.x, ahA); ahA = fma2_(a1, wh.y, ahA);
            ahB = fma2_(b0, wh.x, ahB); ahB = fma2_(b1, wh.y, ahB);
        }
        {   // tail input j=8
            u64 wz8 = bz[8], wr8 = br[8], wh8 = bh[8];
            u64 a8 = x2A[8], b8 = x2B[8];
            azA = fma2_(a8, wz8, azA); azB = fma2_(b8, wz8, azB);
            arA = fma2_(a8, wr8, arA); arB = fma2_(b8, wr8, arB);
            ahA = fma2_(a8, wh8, ahA); ahB = fma2_(b8, wh8, ahB);
        }
        const u64* qz = s_prkT + (size_t)u * 10;
        const u64* qr = s_prkT + (size_t)(10 + u) * 10;
        const u64* qh = s_prkT + (size_t)(20 + u) * 10;
        #pragma unroll
        for (int jp = 0; jp < 5; jp++) {
            ulonglong2 wz = ((const ulonglong2*)qz)[jp];
            ulonglong2 wr = ((const ulonglong2*)qr)[jp];
            ulonglong2 wh = ((const ulonglong2*)qh)[jp];
            u64 a0 = hpA[2 * jp], a1 = hpA[2 * jp + 1];
            u64 b0 = hpB[2 * jp], b1 = hpB[2 * jp + 1];
            rzA = fma2_(a0, wz.x, rzA); rzA = fma2_(a1, wz.y, rzA);
            rzB = fma2_(b0, wz.x, rzB); rzB = fma2_(b1, wz.y, rzB);
            rrA = fma2_(a0, wr.x, rrA); rrA = fma2_(a1, wr.y, rrA);
            rrB = fma2_(b0, wr.x, rrB); rrB = fma2_(b1, wr.y, rrB);
            rhA = fma2_(a0, wh.x, rhA); rhA = fma2_(a1, wh.y, rhA);
            rhB = fma2_(b0, wh.x, rhB); rhB = fma2_(b1, wh.y, rhB);
        }
        u64 zA = sig2(add2_(azA, rzA));
        u64 rA = sig2(add2_(arA, rrA));
        u64 hhA = tanh2(fma2_(rA, rhA, ahA));
        u64 hnA = fma2_(zA, sub2_(hpA[u], hhA), hhA);
        u64 zB = sig2(add2_(azB, rzB));
        u64 rB = sig2(add2_(arB, rrB));
        u64 hhB = tanh2(fma2_(rB, rhB, ahB));
        u64 hnB = fma2_(zB, sub2_(hpB[u], hhB), hhB);
        float a0, a1, a2, a3;
        unpack2(hnA, a0, a1); unpack2(hnB, a2, a3);
        s_hp[t * 11 + u]              = a0;
        s_hp[(t + 128) * 11 + u]      = a1;
        s_hp[(t + 256) * 11 + u]      = a2;
        s_hp[(t + 384) * 11 + u]      = a3;
        vals[9 + u] = (a0 + a1) + (a2 + a3);
    }

    // ---- deterministic block reduction of 20 values ----
    int lane = t & 31, warp = t >> 5;
    #pragma unroll
    for (int v = 0; v < 20; v++) {
        float a = vals[v];
        #pragma unroll
        for (int o = 16; o > 0; o >>= 1) a += __shfl_xor_sync(0xffffffffu, a, o);
        if (lane == 0) s_red[v * 4 + warp] = a;
    }
    __syncthreads();

    // coalesced store of h_param_new from padded stage
    {
        float4* dst = (float4*)(out + (size_t)9 * N_TOT + (size_t)gp0 * 10);
        #pragma unroll
        for (int q = 0; q < 10; q++) {
            int k = t + q * TPB;
            int i0 = 4 * k;
            float4 v;
            v.x = s_hp[i0     + (i0    ) / 10];
            v.y = s_hp[i0 + 1 + (i0 + 1) / 10];
            v.z = s_hp[i0 + 2 + (i0 + 2) / 10];
            v.w = s_hp[i0 + 3 + (i0 + 3) / 10];
            dst[k] = v;
        }
    }
    if (t < 20) {
        float a = (s_red[t * 4] + s_red[t * 4 + 1]) + (s_red[t * 4 + 2] + s_red[t * 4 + 3]);
        g_part[t * K2_BLOCKS + blockIdx.x] = a;
    }
}

// ---------------- k34: reduce + finalize + spin-scaled delta (one launch) ----------------
__global__ void k34_fused(const float* __restrict__ ht, const float* __restrict__ hg,
                          const float* __restrict__ tk, const float* __restrict__ trk,
                          const float* __restrict__ tb, float* __restrict__ out) {
    __shared__ float sh[256];
    __shared__ bool last;
    int t = threadIdx.x, b = blockIdx.x;

    if (b < 20) {
        float a = 0.f;
        #pragma unroll
        for (int k = 0; k < K2_BLOCKS / 256; k++) a += g_part[b * K2_BLOCKS + t + k * 256];
        sh[t] = a; __syncthreads();
        for (int st = 128; st > 0; st >>= 1) { if (t < st) sh[t] += sh[t + st]; __syncthreads(); }
        if (t == 0) {
            g_fin[b] = sh[0];
            __threadfence();
            last = (atomicAdd(&g_doneB, 1u) == 19u);
        }
        __syncthreads();
        if (last && t == 0) {
            g_doneB = 0u;
            float inv = 1.f / (float)N_TOT;
            float sc = (float)N_TOT * rsqrtf(g_fin[19]);
            g_scale = sc;

            float ti[24];
            for (int j = 0; j < 19; j++) ti[j] = g_fin[j] * inv;
            for (int j = 0; j < 5; j++)  ti[19 + j] = hg[j];

            float xs[15], rs[15];
            for (int k = 0; k < 15; k++) { xs[k] = tb[k]; rs[k] = tb[15 + k]; }
            for (int j = 0; j < 24; j++) {
                float xj = ti[j];
                for (int k = 0; k < 15; k++) xs[k] += xj * tk[j * 15 + k];
            }
            for (int u = 0; u < 5; u++) {
                float hu = ht[u];
                for (int k = 0; k < 15; k++) rs[k] += hu * trk[u * 15 + k];
            }
            float htn[5];
            for (int u = 0; u < 5; u++) {
                float z  = sig1(xs[u] + rs[u]);
                float r  = sig1(xs[5 + u] + rs[5 + u]);
                float hh = tanhap(xs[10 + u] + r * rs[10 + u]);
                htn[u] = z * ht[u] + (1.f - z) * hh;
                out[(size_t)19 * N_TOT + u] = htn[u];
            }
            size_t go = (size_t)21 * N_TOT + 5;
            for (int j = 0; j < 19; j++) out[go + j] = ti[j];
            for (int u = 0; u < 5; u++)  out[go + 19 + u] = htn[u];
            __threadfence();
            atomicExch(&g_flag, 1u);     // release: scale is ready
        }
    }

    // ---- all blocks: wait for scale, then scale this block's delta chunk ----
    if (t == 0) {
        volatile unsigned* f = &g_flag;
        while (*f == 0u) { }
        sh[0] = 0.f;   // dummy write to order the spin before the barrier
    }
    __syncthreads();
    __threadfence();   // acquire: make finalize's g_scale visible
    float s = g_scale;
    float4* o4 = (float4*)out;
    int idx = b * 256 + t;
    float4 v = o4[idx];
    v.x *= s; v.y *= s; v.z *= s; v.w *= s;
    o4[idx] = v;
}

extern "C" void kernel_launch(void* const* d_in, const int* in_sizes, int n_in,
                              void* d_out, int out_size) {
    (void)in_sizes; (void)n_in; (void)out_size;
    const float* grads = (const float*)d_in[1];
    const float* gbar  = (const float*)d_in[2];
    const float* lam   = (const float*)d_in[3];
    const float* hp    = (const float*)d_in[4];
    const float* ht    = (const float*)d_in[5];
    const float* hg    = (const float*)d_in[6];
    const float* nubar = (const float*)d_in[7];
    const float* lr    = (const float*)d_in[8];
    const float* pk    = (const float*)d_in[9];
    const float* prk   = (const float*)d_in[10];
    const float* pb    = (const float*)d_in[11];
    const float* tk    = (const float*)d_in[12];
    const float* trk   = (const float*)d_in[13];
    const float* tb    = (const float*)d_in[14];
    const float* w_dt  = (const float*)d_in[15];
    const float* b_dt  = (const float*)d_in[16];
    const float* w_dn  = (const float*)d_in[17];
    const float* b_dn  = (const float*)d_in[18];
    const float* w_bg  = (const float*)d_in[19];
    const float* b_bg  = (const float*)d_in[20];
    const float* w_bl  = (const float*)d_in[21];
    const float* b_bl  = (const float*)d_in[22];
    const float* gmm   = (const float*)d_in[23];
    float* out = (float*)d_out;

    kA_setup<<<K1_BLOCKS, 256>>>(lr, ht, hg, pk, prk, pb, w_dt, b_dt, w_dn, b_dn,
                                 w_bg, b_bg, w_bl, b_bl, gmm);            // launch 0
    k2_main<<<K2_BLOCKS, TPB>>>(grads, gbar, lam, hp, nubar, lr, out);    // launch 1
    k34_fused<<<N_TOT / 1024, 256>>>(ht, hg, tk, trk, tb, out);           // launch 2
}

// round 16
// speedup vs baseline: 1.0331x; 1.0331x over previous
#include <cuda_runtime.h>

typedef unsigned long long u64;

#define N_TOT 2097152
#define TPB 128
#define PPB 512
#define K2_BLOCKS (N_TOT / PPB)          // 4096
#define KA_BLOCKS 256

static __device__ float g_part[20 * K2_BLOCKS];
static __device__ float g_lrpart[KA_BLOCKS];
static __device__ float g_scale;
static __device__ float g_fin[20];
static __device__ unsigned int g_doneA;   // kA last-block counter (self-resetting)
static __device__ unsigned int g_doneB;   // k3 last-block counter (self-resetting)
// weight blob: [0,300) pkT | [300,600) prkT | [600,640) w2 | [640,670) xc2 |
//              [670,700) pb12 | [700,703) packed scalars | pad to 704
static __device__ __align__(16) u64 g_wblob[704];

// ---------- packed f32x2 helpers ----------
__device__ __forceinline__ u64 pack2(float lo, float hi) {
    u64 r; asm("mov.b64 %0,{%1,%2};" : "=l"(r) : "f"(lo), "f"(hi)); return r;
}
__device__ __forceinline__ void unpack2(u64 v, float& lo, float& hi) {
    asm("mov.b64 {%0,%1},%2;" : "=f"(lo), "=f"(hi) : "l"(v));
}
__device__ __forceinline__ u64 fma2_(u64 a, u64 b, u64 c) {
    u64 d; asm("fma.rn.f32x2 %0,%1,%2,%3;" : "=l"(d) : "l"(a), "l"(b), "l"(c)); return d;
}
__device__ __forceinline__ u64 add2_(u64 a, u64 b) {
    u64 d; asm("add.rn.f32x2 %0,%1,%2;" : "=l"(d) : "l"(a), "l"(b)); return d;
}
__device__ __forceinline__ u64 mul2_(u64 a, u64 b) {
    u64 d; asm("mul.rn.f32x2 %0,%1,%2;" : "=l"(d) : "l"(a), "l"(b)); return d;
}
__device__ __forceinline__ u64 neg2_(u64 a) { return a ^ 0x8000000080000000ULL; }
__device__ __forceinline__ u64 sub2_(u64 a, u64 b) { return add2_(a, neg2_(b)); }

__device__ __forceinline__ float tanhap(float x) {
    float y; asm("tanh.approx.f32 %0,%1;" : "=f"(y) : "f"(x)); return y;
}
__device__ __forceinline__ float sig1(float x) {
    return fmaf(tanhap(0.5f * x), 0.5f, 0.5f);
}
__device__ __forceinline__ u64 sig2(u64 v) {
    float a, b; unpack2(v, a, b);
    return pack2(sig1(a), sig1(b));
}
__device__ __forceinline__ u64 tanh2(u64 v) {
    float a, b; unpack2(v, a, b);
    return pack2(tanhap(a), tanhap(b));
}
__device__ __forceinline__ u64 sqrt2_(u64 v) {
    float a, b; unpack2(v, a, b);
    float ra, rb;
    asm("sqrt.approx.f32 %0,%1;" : "=f"(ra) : "f"(a));
    asm("sqrt.approx.f32 %0,%1;" : "=f"(rb) : "f"(b));
    return pack2(ra, rb);
}
__device__ __forceinline__ u64 rsqrt2_(u64 v) {
    float a, b; unpack2(v, a, b);
    return pack2(rsqrtf(a), rsqrtf(b));
}
__device__ __forceinline__ u64 log2f2_(u64 v) {
    float a, b; unpack2(v, a, b);
    return pack2(__logf(a), __logf(b));
}

// ---------------- kA: fused lr-mean + xs_const + weight blob (high-MLP, last-block) ----------------
__global__ void kA_setup(const float* __restrict__ lr,
                         const float* __restrict__ ht, const float* __restrict__ hg,
                         const float* __restrict__ pk, const float* __restrict__ prk,
                         const float* __restrict__ pb,
                         const float* __restrict__ w_dt, const float* __restrict__ b_dt,
                         const float* __restrict__ w_dn, const float* __restrict__ b_dn,
                         const float* __restrict__ w_bg, const float* __restrict__ b_bg,
                         const float* __restrict__ w_bl, const float* __restrict__ b_bl,
                         const float* __restrict__ gamma_p) {
    __shared__ float sh[256];
    __shared__ float s_xc[30];
    __shared__ float s_mean;
    __shared__ bool last;
    int t = threadIdx.x;
    // 8 front-batched float4 loads per thread (MLP 8): 256 blocks cover N_TOT/4 float4s
    {
        const float4* l4 = (const float4*)lr;
        int base = blockIdx.x * 2048 + t;
        float4 v[8];
        #pragma unroll
        for (int q = 0; q < 8; q++) v[q] = l4[base + q * 256];
        float s = 0.f;
        #pragma unroll
        for (int q = 0; q < 8; q++) s += (v[q].x + v[q].y) + (v[q].z + v[q].w);
        // warp shuffle reduce
        #pragma unroll
        for (int o = 16; o > 0; o >>= 1) s += __shfl_xor_sync(0xffffffffu, s, o);
        if ((t & 31) == 0) sh[t >> 5] = s;
    }
    __syncthreads();
    if (t == 0) {
        float p = 0.f;
        #pragma unroll
        for (int w = 0; w < 8; w++) p += sh[w];
        g_lrpart[blockIdx.x] = p;
        __threadfence();
        last = (atomicAdd(&g_doneA, 1u) == (unsigned)(KA_BLOCKS - 1));
    }
    __syncthreads();
    if (!last) return;

    // ----- sole surviving block: finalize everything -----
    sh[t] = g_lrpart[t];
    __syncthreads();
    for (int st = 128; st > 0; st >>= 1) { if (t < st) sh[t] += sh[t + st]; __syncthreads(); }
    if (t == 0) {
        s_mean = sh[0] * (1.f / (float)N_TOT);
        g_doneA = 0u;
    }
    if (t < 30) {
        float a = pb[t];
        #pragma unroll
        for (int j = 0; j < 5; j++) a += ht[j] * pk[(9 + j) * 30 + t];
        #pragma unroll
        for (int j = 0; j < 5; j++) a += hg[j] * pk[(14 + j) * 30 + t];
        s_xc[t] = a;
    }
    __syncthreads();

    for (int k = t; k < 300; k += 256) {
        int j = k % 10, gu = k / 10;
        float wA = (j < 9) ? pk[j * 30 + gu] : 0.f;
        g_wblob[k] = pack2(wA, wA);
        float wB = prk[j * 30 + gu];
        g_wblob[300 + k] = pack2(wB, wB);
    }
    if (t < 10) {
        float a = w_dt[t]; g_wblob[600 + t] = pack2(a, a);
        float b = w_dn[t]; g_wblob[610 + t] = pack2(b, b);
        float c = w_bg[t]; g_wblob[620 + t] = pack2(c, c);
        float d = w_bl[t]; g_wblob[630 + t] = pack2(d, d);
    }
    if (t >= 32 && t < 62) {
        int u = t - 32;
        float a = s_xc[u];    g_wblob[640 + u] = pack2(a, a);
        float b = pb[30 + u]; g_wblob[670 + u] = pack2(b, b);
    }
    if (t == 0) {
        g_wblob[700] = pack2(s_mean, gamma_p[0]);
        g_wblob[701] = pack2(b_dt[0], b_dn[0]);
        g_wblob[702] = pack2(b_bg[0], b_bl[0]);
        g_wblob[703] = 0ULL;
    }
}

// ---------------- k2: main pass — byte-identical to R9 (best: 104.9us) ----------------
__global__ __launch_bounds__(TPB, 3)
void k2_main(const float* __restrict__ grads, const float* __restrict__ gbar,
             const float* __restrict__ lam, const float* __restrict__ hp_in,
             const float* __restrict__ nubar, const float* __restrict__ lr_in,
             float* __restrict__ out)
{
    __shared__ __align__(16) u64 s_w[704];
    __shared__ float s_red[20 * 4];
    __shared__ __align__(16) float s_hp[PPB * 11];   // row stride 11 -> conflict-free

    int t = threadIdx.x;
    int gp0 = blockIdx.x * PPB;
    int i = gp0 + t;          // params: i, i+128, i+256, i+384

    // ===== front-batched global loads (maximize MLP before any barrier) =====
    float4 hpv[10];
    {
        const float4* src = (const float4*)(hp_in + (size_t)gp0 * 10);
        #pragma unroll
        for (int q = 0; q < 10; q++) hpv[q] = src[t + q * TPB];
    }
    float grv[4], nbv[4], lrv[4];
    float gbv[16], lmv[16];
    #pragma unroll
    for (int q = 0; q < 4; q++) {
        grv[q] = grads[i + 128 * q];
        nbv[q] = nubar[i + 128 * q];
        lrv[q] = lr_in[i + 128 * q];
    }
    #pragma unroll
    for (int s = 0; s < 4; s++) {
        size_t off = (size_t)s * N_TOT + i;
        #pragma unroll
        for (int q = 0; q < 4; q++) {
            gbv[4 * s + q] = gbar[off + 128 * q];
            lmv[4 * s + q] = lam[off + 128 * q];
        }
    }

    // weight blob copy (gmem, L2-hot after wave 1): 352 float4
    {
        const float4* src = (const float4*)g_wblob;
        float4* dst = (float4*)s_w;
        #pragma unroll
        for (int q = 0; q < 3; q++) {
            int k = t + q * TPB;
            if (k < 352) dst[k] = src[k];
        }
    }

    // stage h_param into padded smem
    #pragma unroll
    for (int q = 0; q < 10; q++) {
        int k = t + q * TPB;
        float4 v = hpv[q];
        int i0 = 4 * k;
        s_hp[i0     + (i0    ) / 10] = v.x;
        s_hp[i0 + 1 + (i0 + 1) / 10] = v.y;
        s_hp[i0 + 2 + (i0 + 2) / 10] = v.z;
        s_hp[i0 + 3 + (i0 + 3) / 10] = v.w;
    }
    __syncthreads();

    const u64* s_pkT  = s_w;
    const u64* s_prkT = s_w + 300;
    const u64* s_w2   = s_w + 600;
    const u64* s_xc2  = s_w + 640;
    const u64* s_pb12 = s_w + 670;
    float ml, gmm, bdt, bdn, bbg, bbl;
    unpack2(s_w[700], ml, gmm);
    unpack2(s_w[701], bdt, bdn);
    unpack2(s_w[702], bbg, bbl);

    u64 hpA[10], hpB[10];
    {
        const float* h0 = s_hp + t * 11;
        #pragma unroll
        for (int u = 0; u < 10; u++) {
            hpA[u] = pack2(h0[u], h0[128 * 11 + u]);
            hpB[u] = pack2(h0[256 * 11 + u], h0[384 * 11 + u]);
        }
    }

    // four dots over h_param (packed, both pair-sets)
    u64 ddtA = pack2(bdt, bdt), ddtB = ddtA;
    u64 ddnA = pack2(bdn, bdn), ddnB = ddnA;
    u64 dbgA = pack2(bbg, bbg), dbgB = dbgA;
    u64 dblA = pack2(bbl, bbl), dblB = dblA;
    #pragma unroll
    for (int u = 0; u < 10; u++) {
        u64 w0 = s_w2[u], w1 = s_w2[10 + u], w2 = s_w2[20 + u], w3 = s_w2[30 + u];
        u64 hA = hpA[u], hB = hpB[u];
        ddtA = fma2_(hA, w0, ddtA); ddtB = fma2_(hB, w0, ddtB);
        ddnA = fma2_(hA, w1, ddnA); ddnB = fma2_(hB, w1, ddnB);
        dbgA = fma2_(hA, w2, dbgA); dbgB = fma2_(hB, w2, dbgB);
        dblA = fma2_(hA, w3, dblA); dblB = fma2_(hB, w3, dblB);
    }
    u64 b1A = sig2(dbgA), b1B = sig2(dbgB);
    u64 b2A = sig2(dblA), b2B = sig2(dblB);

    u64 gA = pack2(grv[0], grv[1]);
    u64 gB = pack2(grv[2], grv[3]);
    u64 g2A = mul2_(gA, gA), g2B = mul2_(gB, gB);

    float vals[20];
    u64 x2A[9], x2B[9];
    u64 llA[4], llB[4];
    #pragma unroll
    for (int s = 0; s < 4; s++) {
        size_t off = (size_t)s * N_TOT + i;
        u64 gbA = pack2(gbv[4 * s + 0], gbv[4 * s + 1]);
        u64 gbB = pack2(gbv[4 * s + 2], gbv[4 * s + 3]);
        u64 lmA = pack2(lmv[4 * s + 0], lmv[4 * s + 1]);
        u64 lmB = pack2(lmv[4 * s + 2], lmv[4 * s + 3]);
        u64 gbnA = fma2_(b1A, sub2_(gbA, gA), gA);
        u64 gbnB = fma2_(b1B, sub2_(gbB, gB), gB);
        u64 lmnA = fma2_(b2A, sub2_(lmA, g2A), g2A);
        u64 lmnB = fma2_(b2B, sub2_(lmB, g2B), g2B);
        float a, b;
        unpack2(gbnA, a, b); out[N_TOT + off] = a; out[N_TOT + off + 128] = b;
        unpack2(gbnB, a, b); out[N_TOT + off + 256] = a; out[N_TOT + off + 384] = b;
        unpack2(lmnA, a, b); out[5 * (size_t)N_TOT + off] = a; out[5 * (size_t)N_TOT + off + 128] = b;
        unpack2(lmnB, a, b); out[5 * (size_t)N_TOT + off + 256] = a; out[5 * (size_t)N_TOT + off + 384] = b;
        u64 mA = mul2_(gbnA, rsqrt2_(lmnA));
        u64 mB = mul2_(gbnB, rsqrt2_(lmnB));
        x2A[s] = mA; x2B[s] = mB;
        float m0, m1, m2, m3; unpack2(mA, m0, m1); unpack2(mB, m2, m3);
        vals[s] = (m0 + m1) + (m2 + m3);
        llA[s] = log2f2_(lmnA); llB[s] = log2f2_(lmnB);
        b1A = sqrt2_(b1A); b1B = sqrt2_(b1B);
        b2A = sqrt2_(b2A); b2B = sqrt2_(b2B);
    }
    {
        u64 q = pack2(0.25f, 0.25f);
        u64 lmAm = mul2_(q, add2_(add2_(llA[0], llA[1]), add2_(llA[2], llA[3])));
        u64 lmBm = mul2_(q, add2_(add2_(llB[0], llB[1]), add2_(llB[2], llB[3])));
        #pragma unroll
        for (int s = 0; s < 4; s++) {
            u64 aA = sub2_(llA[s], lmAm), aB = sub2_(llB[s], lmBm);
            x2A[4 + s] = aA; x2B[4 + s] = aB;
            float a0, a1, a2, a3; unpack2(aA, a0, a1); unpack2(aB, a2, a3);
            vals[4 + s] = (a0 + a1) + (a2 + a3);
        }
    }

    {
        float dt[4], dn[4];
        unpack2(ddtA, dt[0], dt[1]); unpack2(ddtB, dt[2], dt[3]);
        unpack2(ddnA, dn[0], dn[1]); unpack2(ddnB, dn[2], dn[3]);
        float nr[4];
        #pragma unroll
        for (int q = 0; q < 4; q++) {
            int p = i + 128 * q;
            float nu = dn[q] + nbv[q];
            out[(size_t)19 * N_TOT + 5 + p] = nu;
            out[(size_t)20 * N_TOT + 5 + p] = gmm * nbv[q] + (1.f - gmm) * nu;
            out[p] = __expf(lrv[q]) * dt[q];
            nr[q] = lrv[q] - ml;
        }
        vals[19] = dt[0] * dt[0] + dt[1] * dt[1] + dt[2] * dt[2] + dt[3] * dt[3];
        vals[8]  = (nr[0] + nr[1]) + (nr[2] + nr[3]);
        x2A[8] = pack2(nr[0], nr[1]);
        x2B[8] = pack2(nr[2], nr[3]);
    }

    // ---- per-param GRU: vectorized transposed weights (8 inputs vec + j=8 tail) ----
    #pragma unroll 1
    for (int u = 0; u < 10; u++) {
        u64 azA = s_xc2[u], arA = s_xc2[10 + u], ahA = s_xc2[20 + u];
        u64 azB = azA, arB = arA, ahB = ahA;
        u64 rzA = s_pb12[u], rrA = s_pb12[10 + u], rhA = s_pb12[20 + u];
        u64 rzB = rzA, rrB = rrA, rhB = rhA;

        const u64* bz = s_pkT + (size_t)u * 10;
        const u64* br = s_pkT + (size_t)(10 + u) * 10;
        const u64* bh = s_pkT + (size_t)(20 + u) * 10;
        #pragma unroll
        for (int jp = 0; jp < 4; jp++) {
            ulonglong2 wz = ((const ulonglong2*)bz)[jp];
            ulonglong2 wr = ((const ulonglong2*)br)[jp];
            ulonglong2 wh = ((const ulonglong2*)bh)[jp];
            u64 a0 = x2A[2 * jp], a1 = x2A[2 * jp + 1];
            u64 b0 = x2B[2 * jp], b1 = x2B[2 * jp + 1];
            azA = fma2_(a0, wz.x, azA); azA = fma2_(a1, wz.y, azA);
            azB = fma2_(b0, wz.x, azB); azB = fma2_(b1, wz.y, azB);
            arA = fma2_(a0, wr.x, arA); arA = fma2_(a1, wr.y, arA);
            arB = fma2_(b0, wr.x, arB); arB = fma2_(b1, wr.y, arB);
            ahA = fma2_(a0, wh.x, ahA); ahA = fma2_(a1, wh.y, ahA);
            ahB = fma2_(b0, wh.x, ahB); ahB = fma2_(b1, wh.y, ahB);
        }
        {   // tail input j=8
            u64 wz8 = bz[8], wr8 = br[8], wh8 = bh[8];
            u64 a8 = x2A[8], b8 = x2B[8];
            azA = fma2_(a8, wz8, azA); azB = fma2_(b8, wz8, azB);
            arA = fma2_(a8, wr8, arA); arB = fma2_(b8, wr8, arB);
            ahA = fma2_(a8, wh8, ahA); ahB = fma2_(b8, wh8, ahB);
        }
        const u64* qz = s_prkT + (size_t)u * 10;
        const u64* qr = s_prkT + (size_t)(10 + u) * 10;
        const u64* qh = s_prkT + (size_t)(20 + u) * 10;
        #pragma unroll
        for (int jp = 0; jp < 5; jp++) {
            ulonglong2 wz = ((const ulonglong2*)qz)[jp];
            ulonglong2 wr = ((const ulonglong2*)qr)[jp];
            ulonglong2 wh = ((const ulonglong2*)qh)[jp];
            u64 a0 = hpA[2 * jp], a1 = hpA[2 * jp + 1];
            u64 b0 = hpB[2 * jp], b1 = hpB[2 * jp + 1];
            rzA = fma2_(a0, wz.x, rzA); rzA = fma2_(a1, wz.y, rzA);
            rzB = fma2_(b0, wz.x, rzB); rzB = fma2_(b1, wz.y, rzB);
            rrA = fma2_(a0, wr.x, rrA); rrA = fma2_(a1, wr.y, rrA);
            rrB = fma2_(b0, wr.x, rrB); rrB = fma2_(b1, wr.y, rrB);
            rhA = fma2_(a0, wh.x, rhA); rhA = fma2_(a1, wh.y, rhA);
            rhB = fma2_(b0, wh.x, rhB); rhB = fma2_(b1, wh.y, rhB);
        }
        u64 zA = sig2(add2_(azA, rzA));
        u64 rA = sig2(add2_(arA, rrA));
        u64 hhA = tanh2(fma2_(rA, rhA, ahA));
        u64 hnA = fma2_(zA, sub2_(hpA[u], hhA), hhA);
        u64 zB = sig2(add2_(azB, rzB));
        u64 rB = sig2(add2_(arB, rrB));
        u64 hhB = tanh2(fma2_(rB, rhB, ahB));
        u64 hnB = fma2_(zB, sub2_(hpB[u], hhB), hhB);
        float a0, a1, a2, a3;
        unpack2(hnA, a0, a1); unpack2(hnB, a2, a3);
        s_hp[t * 11 + u]              = a0;
        s_hp[(t + 128) * 11 + u]      = a1;
        s_hp[(t + 256) * 11 + u]      = a2;
        s_hp[(t + 384) * 11 + u]      = a3;
        vals[9 + u] = (a0 + a1) + (a2 + a3);
    }

    // ---- deterministic block reduction of 20 values ----
    int lane = t & 31, warp = t >> 5;
    #pragma unroll
    for (int v = 0; v < 20; v++) {
        float a = vals[v];
        #pragma unroll
        for (int o = 16; o > 0; o >>= 1) a += __shfl_xor_sync(0xffffffffu, a, o);
        if (lane == 0) s_red[v * 4 + warp] = a;
    }
    __syncthreads();

    // coalesced store of h_param_new from padded stage
    {
        float4* dst = (float4*)(out + (size_t)9 * N_TOT + (size_t)gp0 * 10);
        #pragma unroll
        for (int q = 0; q < 10; q++) {
            int k = t + q * TPB;
            int i0 = 4 * k;
            float4 v;
            v.x = s_hp[i0     + (i0    ) / 10];
            v.y = s_hp[i0 + 1 + (i0 + 1) / 10];
            v.z = s_hp[i0 + 2 + (i0 + 2) / 10];
            v.w = s_hp[i0 + 3 + (i0 + 3) / 10];
            dst[k] = v;
        }
    }
    if (t < 20) {
        float a = (s_red[t * 4] + s_red[t * 4 + 1]) + (s_red[t * 4 + 2] + s_red[t * 4 + 3]);
        g_part[t * K2_BLOCKS + blockIdx.x] = a;
    }
}

// ---------------- k3: fused reduce (20 blocks) + last-block finalize ----------------
__global__ void k3_fused(const float* __restrict__ ht, const float* __restrict__ hg,
                         const float* __restrict__ tk, const float* __restrict__ trk,
                         const float* __restrict__ tb, float* __restrict__ out) {
    __shared__ float sh[256];
    __shared__ bool last;
    int t = threadIdx.x, v = blockIdx.x;
    float a = 0.f;
    #pragma unroll
    for (int k = 0; k < K2_BLOCKS / 256; k++) a += g_part[v * K2_BLOCKS + t + k * 256];
    sh[t] = a; __syncthreads();
    for (int st = 128; st > 0; st >>= 1) { if (t < st) sh[t] += sh[t + st]; __syncthreads(); }
    if (t == 0) {
        g_fin[v] = sh[0];
        __threadfence();
        last = (atomicAdd(&g_doneB, 1u) == 19u);
    }
    __syncthreads();
    if (last && t == 0) {
        g_doneB = 0u;
        float inv = 1.f / (float)N_TOT;
        g_scale = (float)N_TOT * rsqrtf(g_fin[19]);

        float ti[24];
        for (int j = 0; j < 19; j++) ti[j] = g_fin[j] * inv;
        for (int j = 0; j < 5; j++)  ti[19 + j] = hg[j];

        float xs[15], rs[15];
        for (int k = 0; k < 15; k++) { xs[k] = tb[k]; rs[k] = tb[15 + k]; }
        for (int j = 0; j < 24; j++) {
            float xj = ti[j];
            for (int k = 0; k < 15; k++) xs[k] += xj * tk[j * 15 + k];
        }
        for (int u = 0; u < 5; u++) {
            float hu = ht[u];
            for (int k = 0; k < 15; k++) rs[k] += hu * trk[u * 15 + k];
        }
        float htn[5];
        for (int u = 0; u < 5; u++) {
            float z  = sig1(xs[u] + rs[u]);
            float r  = sig1(xs[5 + u] + rs[5 + u]);
            float hh = tanhap(xs[10 + u] + r * rs[10 + u]);
            htn[u] = z * ht[u] + (1.f - z) * hh;
            out[(size_t)19 * N_TOT + u] = htn[u];
        }
        size_t go = (size_t)21 * N_TOT + 5;
        for (int j = 0; j < 19; j++) out[go + j] = ti[j];
        for (int u = 0; u < 5; u++)  out[go + 19 + u] = htn[u];
    }
}

// ---------------- k4: apply delta_theta scale in place (MLP 4) ----------------
__global__ void k4_scale(float* __restrict__ out) {
    int t = threadIdx.x;
    int base = blockIdx.x * 1024 + t;
    float4* o4 = (float4*)out;
    float4 v0 = o4[base];
    float4 v1 = o4[base + 256];
    float4 v2 = o4[base + 512];
    float4 v3 = o4[base + 768];
    float s = g_scale;
    v0.x *= s; v0.y *= s; v0.z *= s; v0.w *= s;
    v1.x *= s; v1.y *= s; v1.z *= s; v1.w *= s;
    v2.x *= s; v2.y *= s; v2.z *= s; v2.w *= s;
    v3.x *= s; v3.y *= s; v3.z *= s; v3.w *= s;
    o4[base]       = v0;
    o4[base + 256] = v1;
    o4[base + 512] = v2;
    o4[base + 768] = v3;
}

extern "C" void kernel_launch(void* const* d_in, const int* in_sizes, int n_in,
                              void* d_out, int out_size) {
    (void)in_sizes; (void)n_in; (void)out_size;
    const float* grads = (const float*)d_in[1];
    const float* gbar  = (const float*)d_in[2];
    const float* lam   = (const float*)d_in[3];
    const float* hp    = (const float*)d_in[4];
    const float* ht    = (const float*)d_in[5];
    const float* hg    = (const float*)d_in[6];
    const float* nubar = (const float*)d_in[7];
    const float* lr    = (const float*)d_in[8];
    const float* pk    = (const float*)d_in[9];
    const float* prk   = (const float*)d_in[10];
    const float* pb    = (const float*)d_in[11];
    const float* tk    = (const float*)d_in[12];
    const float* trk   = (const float*)d_in[13];
    const float* tb    = (const float*)d_in[14];
    const float* w_dt  = (const float*)d_in[15];
    const float* b_dt  = (const float*)d_in[16];
    const float* w_dn  = (const float*)d_in[17];
    const float* b_dn  = (const float*)d_in[18];
    const float* w_bg  = (const float*)d_in[19];
    const float* b_bg  = (const float*)d_in[20];
    const float* w_bl  = (const float*)d_in[21];
    const float* b_bl  = (const float*)d_in[22];
    const float* gmm   = (const float*)d_in[23];
    float* out = (float*)d_out;

    kA_setup<<<KA_BLOCKS, 256>>>(lr, ht, hg, pk, prk, pb, w_dt, b_dt, w_dn, b_dn,
                                 w_bg, b_bg, w_bl, b_bl, gmm);            // launch 0
    k2_main<<<K2_BLOCKS, TPB>>>(grads, gbar, lam, hp, nubar, lr, out);    // launch 1
    k3_fused<<<20, 256>>>(ht, hg, tk, trk, tb, out);                      // launch 2
    k4_scale<<<N_TOT / 4096, 256>>>(out);                                 // launch 3
}

// round 17
// speedup vs baseline: 1.0347x; 1.0015x over previous
#include <cuda_runtime.h>

typedef unsigned long long u64;

#define N_TOT 2097152
#define TPB 128
#define PPB 512
#define K2_BLOCKS (N_TOT / PPB)          // 4096
#define KA_BLOCKS 256

static __device__ float g_part[20 * K2_BLOCKS];
static __device__ float g_lrpart[KA_BLOCKS];
static __device__ float g_scale;
static __device__ float g_fin[20];
static __device__ unsigned int g_doneA;   // kA last-block counter (self-resetting)
static __device__ unsigned int g_doneB;   // k3 last-block counter (self-resetting)
// weight blob: [0,300) pkT | [300,600) prkT | [600,640) w2 | [640,670) xc2 |
//              [670,700) pb12 | [700,703) packed scalars | pad to 704
static __device__ __align__(16) u64 g_wblob[704];

// ---------- packed f32x2 helpers ----------
__device__ __forceinline__ u64 pack2(float lo, float hi) {
    u64 r; asm("mov.b64 %0,{%1,%2};" : "=l"(r) : "f"(lo), "f"(hi)); return r;
}
__device__ __forceinline__ void unpack2(u64 v, float& lo, float& hi) {
    asm("mov.b64 {%0,%1},%2;" : "=f"(lo), "=f"(hi) : "l"(v));
}
__device__ __forceinline__ u64 fma2_(u64 a, u64 b, u64 c) {
    u64 d; asm("fma.rn.f32x2 %0,%1,%2,%3;" : "=l"(d) : "l"(a), "l"(b), "l"(c)); return d;
}
__device__ __forceinline__ u64 add2_(u64 a, u64 b) {
    u64 d; asm("add.rn.f32x2 %0,%1,%2;" : "=l"(d) : "l"(a), "l"(b)); return d;
}
__device__ __forceinline__ u64 mul2_(u64 a, u64 b) {
    u64 d; asm("mul.rn.f32x2 %0,%1,%2;" : "=l"(d) : "l"(a), "l"(b)); return d;
}
__device__ __forceinline__ u64 neg2_(u64 a) { return a ^ 0x8000000080000000ULL; }
__device__ __forceinline__ u64 sub2_(u64 a, u64 b) { return add2_(a, neg2_(b)); }

__device__ __forceinline__ float tanhap(float x) {
    float y; asm("tanh.approx.f32 %0,%1;" : "=f"(y) : "f"(x)); return y;
}
__device__ __forceinline__ float sig1(float x) {
    return fmaf(tanhap(0.5f * x), 0.5f, 0.5f);
}
__device__ __forceinline__ u64 sig2(u64 v) {
    float a, b; unpack2(v, a, b);
    return pack2(sig1(a), sig1(b));
}
__device__ __forceinline__ u64 tanh2(u64 v) {
    float a, b; unpack2(v, a, b);
    return pack2(tanhap(a), tanhap(b));
}
__device__ __forceinline__ u64 sqrt2_(u64 v) {
    float a, b; unpack2(v, a, b);
    float ra, rb;
    asm("sqrt.approx.f32 %0,%1;" : "=f"(ra) : "f"(a));
    asm("sqrt.approx.f32 %0,%1;" : "=f"(rb) : "f"(b));
    return pack2(ra, rb);
}
__device__ __forceinline__ u64 rsqrt2_(u64 v) {
    float a, b; unpack2(v, a, b);
    return pack2(rsqrtf(a), rsqrtf(b));
}
__device__ __forceinline__ u64 log2f2_(u64 v) {
    float a, b; unpack2(v, a, b);
    return pack2(__logf(a), __logf(b));
}

// ---------------- kA: fused lr-mean + xs_const + weight blob (high-MLP, last-block) ----------------
__global__ void kA_setup(const float* __restrict__ lr,
                         const float* __restrict__ ht, const float* __restrict__ hg,
                         const float* __restrict__ pk, const float* __restrict__ prk,
                         const float* __restrict__ pb,
                         const float* __restrict__ w_dt, const float* __restrict__ b_dt,
                         const float* __restrict__ w_dn, const float* __restrict__ b_dn,
                         const float* __restrict__ w_bg, const float* __restrict__ b_bg,
                         const float* __restrict__ w_bl, const float* __restrict__ b_bl,
                         const float* __restrict__ gamma_p) {
    __shared__ float sh[256];
    __shared__ float s_xc[30];
    __shared__ float s_mean;
    __shared__ bool last;
    int t = threadIdx.x;
    {
        const float4* l4 = (const float4*)lr;
        int base = blockIdx.x * 2048 + t;
        float4 v[8];
        #pragma unroll
        for (int q = 0; q < 8; q++) v[q] = l4[base + q * 256];
        float s = 0.f;
        #pragma unroll
        for (int q = 0; q < 8; q++) s += (v[q].x + v[q].y) + (v[q].z + v[q].w);
        #pragma unroll
        for (int o = 16; o > 0; o >>= 1) s += __shfl_xor_sync(0xffffffffu, s, o);
        if ((t & 31) == 0) sh[t >> 5] = s;
    }
    __syncthreads();
    if (t == 0) {
        float p = 0.f;
        #pragma unroll
        for (int w = 0; w < 8; w++) p += sh[w];
        g_lrpart[blockIdx.x] = p;
        __threadfence();
        last = (atomicAdd(&g_doneA, 1u) == (unsigned)(KA_BLOCKS - 1));
    }
    __syncthreads();
    if (!last) return;

    sh[t] = g_lrpart[t];
    __syncthreads();
    for (int st = 128; st > 0; st >>= 1) { if (t < st) sh[t] += sh[t + st]; __syncthreads(); }
    if (t == 0) {
        s_mean = sh[0] * (1.f / (float)N_TOT);
        g_doneA = 0u;
    }
    if (t < 30) {
        float a = pb[t];
        #pragma unroll
        for (int j = 0; j < 5; j++) a += ht[j] * pk[(9 + j) * 30 + t];
        #pragma unroll
        for (int j = 0; j < 5; j++) a += hg[j] * pk[(14 + j) * 30 + t];
        s_xc[t] = a;
    }
    __syncthreads();

    for (int k = t; k < 300; k += 256) {
        int j = k % 10, gu = k / 10;
        float wA = (j < 9) ? pk[j * 30 + gu] : 0.f;
        g_wblob[k] = pack2(wA, wA);
        float wB = prk[j * 30 + gu];
        g_wblob[300 + k] = pack2(wB, wB);
    }
    if (t < 10) {
        float a = w_dt[t]; g_wblob[600 + t] = pack2(a, a);
        float b = w_dn[t]; g_wblob[610 + t] = pack2(b, b);
        float c = w_bg[t]; g_wblob[620 + t] = pack2(c, c);
        float d = w_bl[t]; g_wblob[630 + t] = pack2(d, d);
    }
    if (t >= 32 && t < 62) {
        int u = t - 32;
        float a = s_xc[u];    g_wblob[640 + u] = pack2(a, a);
        float b = pb[30 + u]; g_wblob[670 + u] = pack2(b, b);
    }
    if (t == 0) {
        g_wblob[700] = pack2(s_mean, gamma_p[0]);
        g_wblob[701] = pack2(b_dt[0], b_dn[0]);
        g_wblob[702] = pack2(b_bg[0], b_bl[0]);
        g_wblob[703] = 0ULL;
    }
}

// ---------------- k2: main pass (R9 core) + PDL sync before blob use ----------------
__global__ __launch_bounds__(TPB, 3)
void k2_main(const float* __restrict__ grads, const float* __restrict__ gbar,
             const float* __restrict__ lam, const float* __restrict__ hp_in,
             const float* __restrict__ nubar, const float* __restrict__ lr_in,
             float* __restrict__ out)
{
    __shared__ __align__(16) u64 s_w[704];
    __shared__ float s_red[20 * 4];
    __shared__ __align__(16) float s_hp[PPB * 11];   // row stride 11 -> conflict-free

    int t = threadIdx.x;
    int gp0 = blockIdx.x * PPB;
    int i = gp0 + t;          // params: i, i+128, i+256, i+384

    // ===== front-batched global loads — independent of kA: run during overlap =====
    float4 hpv[10];
    {
        const float4* src = (const float4*)(hp_in + (size_t)gp0 * 10);
        #pragma unroll
        for (int q = 0; q < 10; q++) hpv[q] = src[t + q * TPB];
    }
    float grv[4], nbv[4], lrv[4];
    float gbv[16], lmv[16];
    #pragma unroll
    for (int q = 0; q < 4; q++) {
        grv[q] = grads[i + 128 * q];
        nbv[q] = nubar[i + 128 * q];
        lrv[q] = lr_in[i + 128 * q];
    }
    #pragma unroll
    for (int s = 0; s < 4; s++) {
        size_t off = (size_t)s * N_TOT + i;
        #pragma unroll
        for (int q = 0; q < 4; q++) {
            gbv[4 * s + q] = gbar[off + 128 * q];
            lmv[4 * s + q] = lam[off + 128 * q];
        }
    }

    // stage h_param into padded smem (also independent of kA)
    #pragma unroll
    for (int q = 0; q < 10; q++) {
        int k = t + q * TPB;
        float4 v = hpv[q];
        int i0 = 4 * k;
        s_hp[i0     + (i0    ) / 10] = v.x;
        s_hp[i0 + 1 + (i0 + 1) / 10] = v.y;
        s_hp[i0 + 2 + (i0 + 2) / 10] = v.z;
        s_hp[i0 + 3 + (i0 + 3) / 10] = v.w;
    }

    // ---- PDL: wait for kA before touching the weight blob ----
    cudaGridDependencySynchronize();

    // weight blob copy (L2-hot after wave 1): 352 float4
    {
        const float4* src = (const float4*)g_wblob;
        float4* dst = (float4*)s_w;
        #pragma unroll
        for (int q = 0; q < 3; q++) {
            int k = t + q * TPB;
            if (k < 352) dst[k] = src[k];
        }
    }
    __syncthreads();

    const u64* s_pkT  = s_w;
    const u64* s_prkT = s_w + 300;
    const u64* s_w2   = s_w + 600;
    const u64* s_xc2  = s_w + 640;
    const u64* s_pb12 = s_w + 670;
    float ml, gmm, bdt, bdn, bbg, bbl;
    unpack2(s_w[700], ml, gmm);
    unpack2(s_w[701], bdt, bdn);
    unpack2(s_w[702], bbg, bbl);

    u64 hpA[10], hpB[10];
    {
        const float* h0 = s_hp + t * 11;
        #pragma unroll
        for (int u = 0; u < 10; u++) {
            hpA[u] = pack2(h0[u], h0[128 * 11 + u]);
            hpB[u] = pack2(h0[256 * 11 + u], h0[384 * 11 + u]);
        }
    }

    // four dots over h_param (packed, both pair-sets)
    u64 ddtA = pack2(bdt, bdt), ddtB = ddtA;
    u64 ddnA = pack2(bdn, bdn), ddnB = ddnA;
    u64 dbgA = pack2(bbg, bbg), dbgB = dbgA;
    u64 dblA = pack2(bbl, bbl), dblB = dblA;
    #pragma unroll
    for (int u = 0; u < 10; u++) {
        u64 w0 = s_w2[u], w1 = s_w2[10 + u], w2 = s_w2[20 + u], w3 = s_w2[30 + u];
        u64 hA = hpA[u], hB = hpB[u];
        ddtA = fma2_(hA, w0, ddtA); ddtB = fma2_(hB, w0, ddtB);
        ddnA = fma2_(hA, w1, ddnA); ddnB = fma2_(hB, w1, ddnB);
        dbgA = fma2_(hA, w2, dbgA); dbgB = fma2_(hB, w2, dbgB);
        dblA = fma2_(hA, w3, dblA); dblB = fma2_(hB, w3, dblB);
    }
    u64 b1A = sig2(dbgA), b1B = sig2(dbgB);
    u64 b2A = sig2(dblA), b2B = sig2(dblB);

    u64 gA = pack2(grv[0], grv[1]);
    u64 gB = pack2(grv[2], grv[3]);
    u64 g2A = mul2_(gA, gA), g2B = mul2_(gB, gB);

    float vals[20];
    u64 x2A[9], x2B[9];
    u64 llA[4], llB[4];
    #pragma unroll
    for (int s = 0; s < 4; s++) {
        size_t off = (size_t)s * N_TOT + i;
        u64 gbA = pack2(gbv[4 * s + 0], gbv[4 * s + 1]);
        u64 gbB = pack2(gbv[4 * s + 2], gbv[4 * s + 3]);
        u64 lmA = pack2(lmv[4 * s + 0], lmv[4 * s + 1]);
        u64 lmB = pack2(lmv[4 * s + 2], lmv[4 * s + 3]);
        u64 gbnA = fma2_(b1A, sub2_(gbA, gA), gA);
        u64 gbnB = fma2_(b1B, sub2_(gbB, gB), gB);
        u64 lmnA = fma2_(b2A, sub2_(lmA, g2A), g2A);
        u64 lmnB = fma2_(b2B, sub2_(lmB, g2B), g2B);
        float a, b;
        unpack2(gbnA, a, b); out[N_TOT + off] = a; out[N_TOT + off + 128] = b;
        unpack2(gbnB, a, b); out[N_TOT + off + 256] = a; out[N_TOT + off + 384] = b;
        unpack2(lmnA, a, b); out[5 * (size_t)N_TOT + off] = a; out[5 * (size_t)N_TOT + off + 128] = b;
        unpack2(lmnB, a, b); out[5 * (size_t)N_TOT + off + 256] = a; out[5 * (size_t)N_TOT + off + 384] = b;
        u64 mA = mul2_(gbnA, rsqrt2_(lmnA));
        u64 mB = mul2_(gbnB, rsqrt2_(lmnB));
        x2A[s] = mA; x2B[s] = mB;
        float m0, m1, m2, m3; unpack2(mA, m0, m1); unpack2(mB, m2, m3);
        vals[s] = (m0 + m1) + (m2 + m3);
        llA[s] = log2f2_(lmnA); llB[s] = log2f2_(lmnB);
        b1A = sqrt2_(b1A); b1B = sqrt2_(b1B);
        b2A = sqrt2_(b2A); b2B = sqrt2_(b2B);
    }
    {
        u64 q = pack2(0.25f, 0.25f);
        u64 lmAm = mul2_(q, add2_(add2_(llA[0], llA[1]), add2_(llA[2], llA[3])));
        u64 lmBm = mul2_(q, add2_(add2_(llB[0], llB[1]), add2_(llB[2], llB[3])));
        #pragma unroll
        for (int s = 0; s < 4; s++) {
            u64 aA = sub2_(llA[s], lmAm), aB = sub2_(llB[s], lmBm);
            x2A[4 + s] = aA; x2B[4 + s] = aB;
            float a0, a1, a2, a3; unpack2(aA, a0, a1); unpack2(aB, a2, a3);
            vals[4 + s] = (a0 + a1) + (a2 + a3);
        }
    }

    {
        float dt[4], dn[4];
        unpack2(ddtA, dt[0], dt[1]); unpack2(ddtB, dt[2], dt[3]);
        unpack2(ddnA, dn[0], dn[1]); unpack2(ddnB, dn[2], dn[3]);
        float nr[4];
        #pragma unroll
        for (int q = 0; q < 4; q++) {
            int p = i + 128 * q;
            float nu = dn[q] + nbv[q];
            out[(size_t)19 * N_TOT + 5 + p] = nu;
            out[(size_t)20 * N_TOT + 5 + p] = gmm * nbv[q] + (1.f - gmm) * nu;
            out[p] = __expf(lrv[q]) * dt[q];
            nr[q] = lrv[q] - ml;
        }
        vals[19] = dt[0] * dt[0] + dt[1] * dt[1] + dt[2] * dt[2] + dt[3] * dt[3];
        vals[8]  = (nr[0] + nr[1]) + (nr[2] + nr[3]);
        x2A[8] = pack2(nr[0], nr[1]);
        x2B[8] = pack2(nr[2], nr[3]);
    }

    // ---- per-param GRU: vectorized transposed weights (8 inputs vec + j=8 tail) ----
    #pragma unroll 1
    for (int u = 0; u < 10; u++) {
        u64 azA = s_xc2[u], arA = s_xc2[10 + u], ahA = s_xc2[20 + u];
        u64 azB = azA, arB = arA, ahB = ahA;
        u64 rzA = s_pb12[u], rrA = s_pb12[10 + u], rhA = s_pb12[20 + u];
        u64 rzB = rzA, rrB = rrA, rhB = rhA;

        const u64* bz = s_pkT + (size_t)u * 10;
        const u64* br = s_pkT + (size_t)(10 + u) * 10;
        const u64* bh = s_pkT + (size_t)(20 + u) * 10;
        #pragma unroll
        for (int jp = 0; jp < 4; jp++) {
            ulonglong2 wz = ((const ulonglong2*)bz)[jp];
            ulonglong2 wr = ((const ulonglong2*)br)[jp];
            ulonglong2 wh = ((const ulonglong2*)bh)[jp];
            u64 a0 = x2A[2 * jp], a1 = x2A[2 * jp + 1];
            u64 b0 = x2B[2 * jp], b1 = x2B[2 * jp + 1];
            azA = fma2_(a0, wz.x, azA); azA = fma2_(a1, wz.y, azA);
            azB = fma2_(b0, wz.x, azB); azB = fma2_(b1, wz.y, azB);
            arA = fma2_(a0, wr.x, arA); arA = fma2_(a1, wr.y, arA);
            arB = fma2_(b0, wr.x, arB); arB = fma2_(b1, wr.y, arB);
            ahA = fma2_(a0, wh.x, ahA); ahA = fma2_(a1, wh.y, ahA);
            ahB = fma2_(b0, wh.x, ahB); ahB = fma2_(b1, wh.y, ahB);
        }
        {   // tail input j=8
            u64 wz8 = bz[8], wr8 = br[8], wh8 = bh[8];
            u64 a8 = x2A[8], b8 = x2B[8];
            azA = fma2_(a8, wz8, azA); azB = fma2_(b8, wz8, azB);
            arA = fma2_(a8, wr8, arA); arB = fma2_(b8, wr8, arB);
            ahA = fma2_(a8, wh8, ahA); ahB = fma2_(b8, wh8, ahB);
        }
        const u64* qz = s_prkT + (size_t)u * 10;
        const u64* qr = s_prkT + (size_t)(10 + u) * 10;
        const u64* qh = s_prkT + (size_t)(20 + u) * 10;
        #pragma unroll
        for (int jp = 0; jp < 5; jp++) {
            ulonglong2 wz = ((const ulonglong2*)qz)[jp];
            ulonglong2 wr = ((const ulonglong2*)qr)[jp];
            ulonglong2 wh = ((const ulonglong2*)qh)[jp];
            u64 a0 = hpA[2 * jp], a1 = hpA[2 * jp + 1];
            u64 b0 = hpB[2 * jp], b1 = hpB[2 * jp + 1];
            rzA = fma2_(a0, wz.x, rzA); rzA = fma2_(a1, wz.y, rzA);
            rzB = fma2_(b0, wz.x, rzB); rzB = fma2_(b1, wz.y, rzB);
            rrA = fma2_(a0, wr.x, rrA); rrA = fma2_(a1, wr.y, rrA);
            rrB = fma2_(b0, wr.x, rrB); rrB = fma2_(b1, wr.y, rrB);
            rhA = fma2_(a0, wh.x, rhA); rhA = fma2_(a1, wh.y, rhA);
            rhB = fma2_(b0, wh.x, rhB); rhB = fma2_(b1, wh.y, rhB);
        }
        u64 zA = sig2(add2_(azA, rzA));
        u64 rA = sig2(add2_(arA, rrA));
        u64 hhA = tanh2(fma2_(rA, rhA, ahA));
        u64 hnA = fma2_(zA, sub2_(hpA[u], hhA), hhA);
        u64 zB = sig2(add2_(azB, rzB));
        u64 rB = sig2(add2_(arB, rrB));
        u64 hhB = tanh2(fma2_(rB, rhB, ahB));
        u64 hnB = fma2_(zB, sub2_(hpB[u], hhB), hhB);
        float a0, a1, a2, a3;
        unpack2(hnA, a0, a1); unpack2(hnB, a2, a3);
        s_hp[t * 11 + u]              = a0;
        s_hp[(t + 128) * 11 + u]      = a1;
        s_hp[(t + 256) * 11 + u]      = a2;
        s_hp[(t + 384) * 11 + u]      = a3;
        vals[9 + u] = (a0 + a1) + (a2 + a3);
    }

    // ---- deterministic block reduction of 20 values ----
    int lane = t & 31, warp = t >> 5;
    #pragma unroll
    for (int v = 0; v < 20; v++) {
        float a = vals[v];
        #pragma unroll
        for (int o = 16; o > 0; o >>= 1) a += __shfl_xor_sync(0xffffffffu, a, o);
        if (lane == 0) s_red[v * 4 + warp] = a;
    }
    __syncthreads();

    // coalesced store of h_param_new from padded stage
    {
        float4* dst = (float4*)(out + (size_t)9 * N_TOT + (size_t)gp0 * 10);
        #pragma unroll
        for (int q = 0; q < 10; q++) {
            int k = t + q * TPB;
            int i0 = 4 * k;
            float4 v;
            v.x = s_hp[i0     + (i0    ) / 10];
            v.y = s_hp[i0 + 1 + (i0 + 1) / 10];
            v.z = s_hp[i0 + 2 + (i0 + 2) / 10];
            v.w = s_hp[i0 + 3 + (i0 + 3) / 10];
            dst[k] = v;
        }
    }
    if (t < 20) {
        float a = (s_red[t * 4] + s_red[t * 4 + 1]) + (s_red[t * 4 + 2] + s_red[t * 4 + 3]);
        g_part[t * K2_BLOCKS + blockIdx.x] = a;
    }
}

// ---------------- k3: fused reduce (20 blocks) + last-block finalize ----------------
__global__ void k3_fused(const float* __restrict__ ht, const float* __restrict__ hg,
                         const float* __restrict__ tk, const float* __restrict__ trk,
                         const float* __restrict__ tb, float* __restrict__ out) {
    cudaGridDependencySynchronize();   // PDL: g_part depends on all of k2
    __shared__ float sh[256];
    __shared__ bool last;
    int t = threadIdx.x, v = blockIdx.x;
    float a = 0.f;
    #pragma unroll
    for (int k = 0; k < K2_BLOCKS / 256; k++) a += g_part[v * K2_BLOCKS + t + k * 256];
    sh[t] = a; __syncthreads();
    for (int st = 128; st > 0; st >>= 1) { if (t < st) sh[t] += sh[t + st]; __syncthreads(); }
    if (t == 0) {
        g_fin[v] = sh[0];
        __threadfence();
        last = (atomicAdd(&g_doneB, 1u) == 19u);
    }
    __syncthreads();
    if (last && t == 0) {
        g_doneB = 0u;
        float inv = 1.f / (float)N_TOT;
        g_scale = (float)N_TOT * rsqrtf(g_fin[19]);

        float ti[24];
        for (int j = 0; j < 19; j++) ti[j] = g_fin[j] * inv;
        for (int j = 0; j < 5; j++)  ti[19 + j] = hg[j];

        float xs[15], rs[15];
        for (int k = 0; k < 15; k++) { xs[k] = tb[k]; rs[k] = tb[15 + k]; }
        for (int j = 0; j < 24; j++) {
            float xj = ti[j];
            for (int k = 0; k < 15; k++) xs[k] += xj * tk[j * 15 + k];
        }
        for (int u = 0; u < 5; u++) {
            float hu = ht[u];
            for (int k = 0; k < 15; k++) rs[k] += hu * trk[u * 15 + k];
        }
        float htn[5];
        for (int u = 0; u < 5; u++) {
            float z  = sig1(xs[u] + rs[u]);
            float r  = sig1(xs[5 + u] + rs[5 + u]);
            float hh = tanhap(xs[10 + u] + r * rs[10 + u]);
            htn[u] = z * ht[u] + (1.f - z) * hh;
            out[(size_t)19 * N_TOT + u] = htn[u];
        }
        size_t go = (size_t)21 * N_TOT + 5;
        for (int j = 0; j < 19; j++) out[go + j] = ti[j];
        for (int u = 0; u < 5; u++)  out[go + 19 + u] = htn[u];
    }
}

// ---------------- k4: scale delta; loads overlap k3 via PDL ----------------
__global__ void k4_scale(float* __restrict__ out) {
    int t = threadIdx.x;
    int base = blockIdx.x * 1024 + t;
    float4* o4 = (float4*)out;
    // delta values come from k2 (already complete); load BEFORE waiting on k3
    float4 v0 = o4[base];
    float4 v1 = o4[base + 256];
    float4 v2 = o4[base + 512];
    float4 v3 = o4[base + 768];
    cudaGridDependencySynchronize();   // PDL: only g_scale depends on k3
    float s = g_scale;
    v0.x *= s; v0.y *= s; v0.z *= s; v0.w *= s;
    v1.x *= s; v1.y *= s; v1.z *= s; v1.w *= s;
    v2.x *= s; v2.y *= s; v2.z *= s; v2.w *= s;
    v3.x *= s; v3.y *= s; v3.z *= s; v3.w *= s;
    o4[base]       = v0;
    o4[base + 256] = v1;
    o4[base + 512] = v2;
    o4[base + 768] = v3;
}

extern "C" void kernel_launch(void* const* d_in, const int* in_sizes, int n_in,
                              void* d_out, int out_size) {
    (void)in_sizes; (void)n_in; (void)out_size;
    const float* grads = (const float*)d_in[1];
    const float* gbar  = (const float*)d_in[2];
    const float* lam   = (const float*)d_in[3];
    const float* hp    = (const float*)d_in[4];
    const float* ht    = (const float*)d_in[5];
    const float* hg    = (const float*)d_in[6];
    const float* nubar = (const float*)d_in[7];
    const float* lr    = (const float*)d_in[8];
    const float* pk    = (const float*)d_in[9];
    const float* prk   = (const float*)d_in[10];
    const float* pb    = (const float*)d_in[11];
    const float* tk    = (const float*)d_in[12];
    const float* trk   = (const float*)d_in[13];
    const float* tb    = (const float*)d_in[14];
    const float* w_dt  = (const float*)d_in[15];
    const float* b_dt  = (const float*)d_in[16];
    const float* w_dn  = (const float*)d_in[17];
    const float* b_dn  = (const float*)d_in[18];
    const float* w_bg  = (const float*)d_in[19];
    const float* b_bg  = (const float*)d_in[20];
    const float* w_bl  = (const float*)d_in[21];
    const float* b_bl  = (const float*)d_in[22];
    const float* gmm   = (const float*)d_in[23];
    float* out = (float*)d_out;

    kA_setup<<<KA_BLOCKS, 256>>>(lr, ht, hg, pk, prk, pb, w_dt, b_dt, w_dn, b_dn,
                                 w_bg, b_bg, w_bl, b_bl, gmm);

    cudaLaunchAttribute pdl[1];
    pdl[0].id = cudaLaunchAttributeProgrammaticStreamSerialization;
    pdl[0].val.programmaticStreamSerializationAllowed = 1;

    {
        cudaLaunchConfig_t cfg = {};
        cfg.gridDim = dim3(K2_BLOCKS, 1, 1);
        cfg.blockDim = dim3(TPB, 1, 1);
        cfg.stream = 0;
        cfg.attrs = pdl;
        cfg.numAttrs = 1;
        cudaLaunchKernelEx(&cfg, k2_main, grads, gbar, lam, hp, nubar, lr, out);
    }
    {
        cudaLaunchConfig_t cfg = {};
        cfg.gridDim = dim3(20, 1, 1);
        cfg.blockDim = dim3(256, 1, 1);
        cfg.stream = 0;
        cfg.attrs = pdl;
        cfg.numAttrs = 1;
        cudaLaunchKernelEx(&cfg, k3_fused, ht, hg, tk, trk, tb, out);
    }
    {
        cudaLaunchConfig_t cfg = {};
        cfg.gridDim = dim3(N_TOT / 4096, 1, 1);
        cfg.blockDim = dim3(256, 1, 1);
        cfg.stream = 0;
        cfg.attrs = pdl;
        cfg.numAttrs = 1;
        cudaLaunchKernelEx(&cfg, k4_scale, out);
    }
}